// round 16
// baseline (speedup 1.0000x reference)
#include <cuda_runtime.h>
#include <cuda_bf16.h>
#include <math.h>
#include <stdint.h>

// Problem shape (fixed)
#define Bb   16
#define Ss   4096
#define Dd   768
#define Hh   384
#define KTOK 40
#define KSEL 48
#define Mtot (Bb * Ss)   // 65536

// ---------------------------------------------------------------------------
// Device scratch
// ---------------------------------------------------------------------------
__device__ __nv_bfloat16 g_Wt [(size_t)Hh * Dd];  // W1^T bf16 [n][k]
__device__ float         g_Wtf[(size_t)Hh * Dd];  // W1^T f32  [n][k] (exact)
__device__ float         g_scores[Mtot];          // pre-sigmoid approx scores
__device__ float         g_hex[(size_t)Bb * KSEL * Hh];
__device__ int           g_cand[Bb * KSEL];
__device__ int           g_idx[Bb * KTOK];

// ---------------------------------------------------------------------------
// helpers
// ---------------------------------------------------------------------------
__device__ __forceinline__ uint32_t smem_u32(const void* p) {
    uint32_t a;
    asm("{ .reg .u64 t; cvta.to.shared.u64 t, %1; cvt.u32.u64 %0, t; }"
        : "=r"(a) : "l"(p));
    return a;
}
__device__ __forceinline__ void cp16(uint32_t saddr, const void* gptr) {
    asm volatile("cp.async.cg.shared.global [%0], [%1], 16;"
                 :: "r"(saddr), "l"(gptr));
}
__device__ __forceinline__ void mma_bf16(float* c, const uint32_t* a,
                                         uint32_t b0, uint32_t b1) {
    asm volatile(
        "mma.sync.aligned.m16n8k16.row.col.f32.bf16.bf16.f32 "
        "{%0,%1,%2,%3}, {%4,%5,%6,%7}, {%8,%9}, {%0,%1,%2,%3};"
        : "+f"(c[0]), "+f"(c[1]), "+f"(c[2]), "+f"(c[3])
        : "r"(a[0]), "r"(a[1]), "r"(a[2]), "r"(a[3]), "r"(b0), "r"(b1));
}
#define LDSM4(r, addr)                                                         \
    asm volatile("ldmatrix.sync.aligned.m8n8.x4.shared.b16 "                   \
                 "{%0,%1,%2,%3}, [%4];"                                        \
                 : "=r"((r)[0]), "=r"((r)[1]), "=r"((r)[2]), "=r"((r)[3])      \
                 : "r"(addr))
// pack two f32 -> bf16x2 (low = x, high = y)
__device__ __forceinline__ uint32_t cvtpack(float x, float y) {
    uint32_t r;
    asm("cvt.rn.bf16x2.f32 %0, %1, %2;" : "=r"(r) : "f"(y), "f"(x));
    return r;
}

// ---------------------------------------------------------------------------
// Kernel 0: convert + transpose W1 [768,384] f32 -> g_Wt (bf16), g_Wtf (f32)
// ---------------------------------------------------------------------------
__global__ void convw_kernel(const float* __restrict__ W1) {
    int i = blockIdx.x * blockDim.x + threadIdx.x;
    if (i >= Dd * Hh) return;
    int k = i / Hh, n = i % Hh;
    float v = W1[i];
    g_Wt [(size_t)n * Dd + k] = __float2bfloat16_rn(v);
    g_Wtf[(size_t)n * Dd + k] = v;
}

// ---------------------------------------------------------------------------
// Fused GEMM + score kernel (proven best — DO NOT TOUCH).
// ---------------------------------------------------------------------------
#define GBM 64
#define GBK 32
#define NCH (Dd / GBK)          // 24
#define APITCH 176
#define ABPITCH 80
#define BPITCH 80
#define ABUF (GBM * APITCH)             // 11264
#define ABBUF (GBM * ABPITCH)           // 5120
#define BBUF (Hh * BPITCH)              // 30720
#define OFF_AB (2 * ABUF)               // 22528
#define OFF_B (OFF_AB + ABBUF)          // 27648
#define SMEM_FUSED (OFF_B + 2 * BBUF)   // 89088
#define EPITCH 388

__global__ void __launch_bounds__(256, 2)
gemmscore_kernel(const float* __restrict__ A,  const float* __restrict__ b1,
                 const float* __restrict__ gamma, const float* __restrict__ beta,
                 const float* __restrict__ W2, const float* __restrict__ b2) {
    extern __shared__ char smem[];
    const uint32_t sb = smem_u32(smem);
    const int tid  = threadIdx.x;
    const int lane = tid & 31, wid = tid >> 5;
    const int wm = wid >> 2, wn = wid & 3;
    const int m0 = blockIdx.x * GBM;
    const int qt = lane & 3, rt = lane >> 2;

    float acc[2][12][4];
    #pragma unroll
    for (int mi = 0; mi < 2; mi++)
        #pragma unroll
        for (int ni = 0; ni < 12; ni++)
            #pragma unroll
            for (int j = 0; j < 4; j++) acc[mi][ni][j] = 0.f;

    const int ar = tid >> 3, aj = tid & 7;
    const int ar2 = (tid + 256) >> 3, aj2 = (tid + 256) & 7;

    const int lmat = lane >> 3, lrin = lane & 7;
    const int a_row = (lmat & 1) * 8 + lrin;
    const int a_khi = (lmat >> 1) * 8;
    const int b_row = (lmat >> 1) * 8 + lrin;
    const int b_khi = (lmat & 1) * 8;

    const uint32_t a_addr0 = sb + OFF_AB + (wm * 32 + a_row) * ABPITCH + a_khi * 2;
    const uint32_t a_addr1 = a_addr0 + 16 * ABPITCH;
    const uint32_t b_base  = sb + OFF_B + (wn * 96 + b_row) * BPITCH + b_khi * 2;

    const int cvr = tid >> 2, cvs = tid & 3;

    cp16(sb + ar  * APITCH + aj  * 16, A + (size_t)(m0 + ar)  * Dd + aj  * 4);
    cp16(sb + ar2 * APITCH + aj2 * 16, A + (size_t)(m0 + ar2) * Dd + aj2 * 4);
    #pragma unroll
    for (int i = 0; i < 6; i++) {
        int f = tid + i * 256;
        int n = f >> 2, j = f & 3;
        cp16(sb + OFF_B + n * BPITCH + j * 16, g_Wt + (size_t)n * Dd + j * 8);
    }
    asm volatile("cp.async.commit_group;");

    for (int c = 0; c < NCH; c++) {
        const int s = c & 1;

        if (c + 1 < NCH) {
            const int s1 = (c + 1) & 1;
            const int ko = (c + 1) * GBK;
            cp16(sb + s1 * ABUF + ar  * APITCH + aj  * 16,
                 A + (size_t)(m0 + ar)  * Dd + ko + aj  * 4);
            cp16(sb + s1 * ABUF + ar2 * APITCH + aj2 * 16,
                 A + (size_t)(m0 + ar2) * Dd + ko + aj2 * 4);
            #pragma unroll
            for (int i = 0; i < 6; i++) {
                int f = tid + i * 256;
                int n = f >> 2, j = f & 3;
                cp16(sb + OFF_B + s1 * BBUF + n * BPITCH + j * 16,
                     g_Wt + (size_t)n * Dd + ko + j * 8);
            }
            asm volatile("cp.async.commit_group;");
            asm volatile("cp.async.wait_group 1;");
        } else {
            asm volatile("cp.async.wait_group 0;");
        }
        __syncthreads();

        {
            const char* src = smem + s * ABUF + cvr * APITCH + cvs * 32;
            float4 v0 = *(const float4*)(src);
            float4 v1 = *(const float4*)(src + 16);
            uint4 p;
            p.x = cvtpack(v0.x, v0.y);
            p.y = cvtpack(v0.z, v0.w);
            p.z = cvtpack(v1.x, v1.y);
            p.w = cvtpack(v1.z, v1.w);
            *(uint4*)(smem + OFF_AB + cvr * ABPITCH + cvs * 16) = p;
        }
        __syncthreads();

        const uint32_t bks = b_base + s * BBUF;

        #pragma unroll
        for (int ks = 0; ks < 2; ks++) {
            const int kb2 = ks * 32;
            uint32_t afr[2][4];
            LDSM4(afr[0], a_addr0 + kb2);
            LDSM4(afr[1], a_addr1 + kb2);
            uint32_t bfr[2][4];
            LDSM4(bfr[0], bks + kb2);
            #pragma unroll
            for (int np = 0; np < 6; np++) {
                if (np < 5)
                    LDSM4(bfr[(np + 1) & 1], bks + (np + 1) * (16 * BPITCH) + kb2);
                const uint32_t* bf = bfr[np & 1];
                mma_bf16(acc[0][2 * np],     afr[0], bf[0], bf[1]);
                mma_bf16(acc[0][2 * np + 1], afr[0], bf[2], bf[3]);
                mma_bf16(acc[1][2 * np],     afr[1], bf[0], bf[1]);
                mma_bf16(acc[1][2 * np + 1], afr[1], bf[2], bf[3]);
            }
        }
        __syncthreads();
    }

    float* eb = (float*)smem;
    float gm[12], bt[12], w2r[12], b1r[12];
    #pragma unroll
    for (int i = 0; i < 12; i++) {
        int j = lane + 32 * i;
        gm[i]  = gamma[j];
        bt[i]  = beta[j];
        w2r[i] = W2[j];
        b1r[i] = b1[j];
    }
    const float b2v = b2[0];

    #pragma unroll
    for (int p = 0; p < 2; p++) {
        if (wm == p) {
            #pragma unroll
            for (int mi = 0; mi < 2; mi++) {
                #pragma unroll
                for (int ni = 0; ni < 12; ni++) {
                    int rl  = mi * 16 + rt;
                    int col = wn * 96 + ni * 8 + 2 * qt;
                    *(float2*)&eb[rl * EPITCH + col] =
                        make_float2(acc[mi][ni][0], acc[mi][ni][1]);
                    *(float2*)&eb[(rl + 8) * EPITCH + col] =
                        make_float2(acc[mi][ni][2], acc[mi][ni][3]);
                }
            }
        }
        __syncthreads();
        #pragma unroll
        for (int rr = 0; rr < 4; rr++) {
            const int rowl = wid * 4 + rr;
            float x[12];
            float sum = 0.f;
            #pragma unroll
            for (int i = 0; i < 12; i++) {
                x[i] = eb[rowl * EPITCH + lane + 32 * i] + b1r[i];
                sum += x[i];
            }
            #pragma unroll
            for (int o = 16; o > 0; o >>= 1) sum += __shfl_xor_sync(0xffffffffu, sum, o);
            const float mu = sum * (1.0f / Hh);
            float sq = 0.f;
            #pragma unroll
            for (int i = 0; i < 12; i++) { float d = x[i] - mu; sq += d * d; }
            #pragma unroll
            for (int o = 16; o > 0; o >>= 1) sq += __shfl_xor_sync(0xffffffffu, sq, o);
            const float rstd = 1.0f / sqrtf(sq * (1.0f / Hh) + 1e-5f);
            float dot = 0.f;
            #pragma unroll
            for (int i = 0; i < 12; i++) {
                float xn = (x[i] - mu) * rstd * gm[i] + bt[i];
                float ge = 0.5f * xn * (1.0f + erff(xn * 0.70710678118654752f));
                dot += ge * w2r[i];
            }
            #pragma unroll
            for (int o = 16; o > 0; o >>= 1) dot += __shfl_xor_sync(0xffffffffu, dot, o);
            if (lane == 0)
                g_scores[m0 + p * 32 + rowl] = dot + b2v;
        }
        __syncthreads();
    }
}

// ---------------------------------------------------------------------------
// monotonic u64 key: (order-preserving f32) << 32 | (Ss-1-i)  (tie -> low i)
// ---------------------------------------------------------------------------
__device__ __forceinline__ unsigned long long score_key(float f, int i) {
    uint32_t b = __float_as_uint(f);
    uint32_t flip = (b & 0x80000000u) ? ~b : (b | 0x80000000u);
    return ((unsigned long long)flip << 32) | (uint32_t)(Ss - 1 - i);
}

// ---------------------------------------------------------------------------
// top-48 per batch with per-warp max caching (proven — DO NOT TOUCH).
// ---------------------------------------------------------------------------
__global__ void __launch_bounds__(256)
topk_kernel() {
    __shared__ float s[Ss];
    __shared__ unsigned long long wkey[8];
    __shared__ int sbw;
    const int b = blockIdx.x;
    const int t = threadIdx.x;
    const int lane = t & 31, wid = t >> 5;

    for (int i = t; i < Ss; i += 256) s[i] = g_scores[b * Ss + i];
    __syncthreads();

    {
        unsigned long long best = 0ull;
        #pragma unroll
        for (int u = 0; u < 16; u++) {
            int i = wid * 512 + u * 32 + lane;
            unsigned long long k = score_key(s[i], i);
            if (k > best) best = k;
        }
        #pragma unroll
        for (int o = 16; o > 0; o >>= 1) {
            unsigned long long ok = __shfl_xor_sync(0xffffffffu, best, o);
            if (ok > best) best = ok;
        }
        if (lane == 0) wkey[wid] = best;
    }
    __syncthreads();

    for (int sel = 0; sel < KSEL; sel++) {
        if (t < 8) {
            unsigned long long v = wkey[t];
            int w = t;
            #pragma unroll
            for (int o = 4; o > 0; o >>= 1) {
                unsigned long long ov = __shfl_xor_sync(0xffu, v, o, 8);
                int ow = __shfl_xor_sync(0xffu, w, o, 8);
                if (ov > v) { v = ov; w = ow; }
            }
            if (t == 0) {
                int idx = Ss - 1 - (int)(v & 0xFFFFFFFFu);
                g_cand[b * KSEL + sel] = idx;
                s[idx] = -3e38f;
                sbw = w;
            }
        }
        __syncthreads();
        const int wb = sbw;
        if (wid == wb) {
            unsigned long long best = 0ull;
            #pragma unroll
            for (int u = 0; u < 16; u++) {
                int i = wb * 512 + u * 32 + lane;
                unsigned long long k = score_key(s[i], i);
                if (k > best) best = k;
            }
            #pragma unroll
            for (int o = 16; o > 0; o >>= 1) {
                unsigned long long ok = __shfl_xor_sync(0xffffffffu, best, o);
                if (ok > best) best = ok;
            }
            if (lane == 0) wkey[wb] = best;
        }
        __syncthreads();
    }
}

// ---------------------------------------------------------------------------
// rescore GEMM v3: exact fp32 h for 768 candidates, deeper grid for latency.
//   512 blocks = (batch 16) x (token-group 8, 6 tokens) x (col-quarter 4).
//   384 threads = (k-eighth 8) x (col-pair 48).  Static smem 36KB, ~50 regs
//   -> 3+ CTAs/SM and 512 blocks actually fill that depth.
// ---------------------------------------------------------------------------
__global__ void __launch_bounds__(384)
rescore_gemm_kernel(const float* __restrict__ features, const float* __restrict__ b1) {
    __shared__ float feat[6 * Dd];             // 18432 B
    __shared__ float part[8 * 6 * 96];         // 18432 B

    const int blk = blockIdx.x;
    const int b   = blk >> 5;
    const int grp = (blk >> 2) & 7;
    const int cq  = blk & 3;
    const int t = threadIdx.x;
    const int kq = t / 48;                     // 0..7
    const int cp = t % 48;                     // col pair 0..47
    const int c0l = cp * 2;
    const int col0 = cq * 96 + c0l;

    const int cbase = b * KSEL + grp * 6;
    #pragma unroll
    for (int j = 0; j < 6; j++) {
        int tok = g_cand[cbase + j];
        const float* src = features + ((size_t)b * Ss + tok) * Dd;
        for (int k = t; k < Dd; k += 384) feat[j * Dd + k] = src[k];
    }
    __syncthreads();

    float acc[6][2];
    #pragma unroll
    for (int j = 0; j < 6; j++) { acc[j][0] = 0.f; acc[j][1] = 0.f; }

    const float4* w0p = (const float4*)(g_Wtf + (size_t)col0 * Dd) + kq * 24;
    const float4* w1p = (const float4*)(g_Wtf + (size_t)(col0 + 1) * Dd) + kq * 24;
    #pragma unroll 4
    for (int it = 0; it < 24; it++) {
        float4 w0 = w0p[it];
        float4 w1 = w1p[it];
        #pragma unroll
        for (int j = 0; j < 6; j++) {
            float4 f = *((const float4*)(feat + j * Dd + kq * 96) + it);
            acc[j][0] = fmaf(f.x, w0.x, fmaf(f.y, w0.y,
                        fmaf(f.z, w0.z, fmaf(f.w, w0.w, acc[j][0]))));
            acc[j][1] = fmaf(f.x, w1.x, fmaf(f.y, w1.y,
                        fmaf(f.z, w1.z, fmaf(f.w, w1.w, acc[j][1]))));
        }
    }
    #pragma unroll
    for (int j = 0; j < 6; j++) {
        part[(kq * 6 + j) * 96 + c0l]     = acc[j][0];
        part[(kq * 6 + j) * 96 + c0l + 1] = acc[j][1];
    }
    __syncthreads();

    for (int idx = t; idx < 6 * 96; idx += 384) {
        int j = idx / 96, c = idx % 96;
        float h = b1[cq * 96 + c];
        #pragma unroll
        for (int q = 0; q < 8; q++) h += part[(q * 6 + j) * 96 + c];
        g_hex[(size_t)(cbase + j) * Hh + cq * 96 + c] = h;
    }
}

// ---------------------------------------------------------------------------
// merged rescore-LN + warp-parallel select: 16 blocks, 384 threads (proven).
// ---------------------------------------------------------------------------
__global__ void __launch_bounds__(384)
lnselect_kernel(const float* __restrict__ gamma, const float* __restrict__ beta,
                const float* __restrict__ W2, const float* __restrict__ b2) {
    __shared__ unsigned long long skey[KSEL];
    const int b    = blockIdx.x;
    const int lane = threadIdx.x & 31, wid = threadIdx.x >> 5;
    const float b2v = b2[0];

    for (int r = 0; r < 4; r++) {
        const int ci   = wid * 4 + r;          // 0..47
        const int cand = b * KSEL + ci;
        const float* row = g_hex + (size_t)cand * Hh;

        float x[12];
        float sum = 0.f;
        #pragma unroll
        for (int i = 0; i < 12; i++) { x[i] = row[lane + 32 * i]; sum += x[i]; }
        #pragma unroll
        for (int o = 16; o > 0; o >>= 1) sum += __shfl_xor_sync(0xffffffffu, sum, o);
        const float mu = sum * (1.0f / Hh);
        float sq = 0.f;
        #pragma unroll
        for (int i = 0; i < 12; i++) { float d = x[i] - mu; sq += d * d; }
        #pragma unroll
        for (int o = 16; o > 0; o >>= 1) sq += __shfl_xor_sync(0xffffffffu, sq, o);
        const float rstd = 1.0f / sqrtf(sq * (1.0f / Hh) + 1e-5f);
        float dot = 0.f;
        #pragma unroll
        for (int i = 0; i < 12; i++) {
            float xn = (x[i] - mu) * rstd * gamma[lane + 32 * i] + beta[lane + 32 * i];
            float ge = 0.5f * xn * (1.0f + erff(xn * 0.70710678118654752f));
            dot += ge * W2[lane + 32 * i];
        }
        #pragma unroll
        for (int o = 16; o > 0; o >>= 1) dot += __shfl_xor_sync(0xffffffffu, dot, o);
        if (lane == 0)
            skey[ci] = score_key(dot + b2v, g_cand[b * KSEL + ci]);
    }
    __syncthreads();

    if (wid == 0) {
        unsigned long long k0 = skey[lane];
        unsigned long long k1 = (lane < KSEL - 32) ? skey[lane + 32] : 0ull;
        for (int sel = 0; sel < KTOK; sel++) {
            unsigned long long m = (k0 > k1) ? k0 : k1;
            unsigned long long w = m;
            #pragma unroll
            for (int o = 16; o > 0; o >>= 1) {
                unsigned long long ow = __shfl_xor_sync(0xffffffffu, w, o);
                if (ow > w) w = ow;
            }
            if (lane == 0)
                g_idx[b * KTOK + sel] = Ss - 1 - (int)(w & 0xFFFFFFFFu);
            if (k0 == w) k0 = 0ull;
            if (k1 == w) k1 = 0ull;
        }
    }
}

// ---------------------------------------------------------------------------
// gather tokens + indices into d_out; each block also zeroes a tail slice
// ---------------------------------------------------------------------------
__global__ void __launch_bounds__(192)
gather_kernel(const float* __restrict__ features, float* __restrict__ out,
              long long out_size) {
    const int blk = blockIdx.x;
    const int b   = blk / KTOK;
    const int tok = g_idx[blk];
    const int t   = threadIdx.x;
    long long base = (long long)blk * Dd;
    if (base + (t + 1) * 4 <= out_size) {
        const float4* src = (const float4*)(features + ((size_t)b * Ss + tok) * Dd);
        ((float4*)(out + base))[t] = src[t];
    }
    if (t == 0) {
        long long pos = (long long)Bb * KTOK * Dd + blk;
        if (pos < out_size) out[pos] = (float)tok;
    }
    const long long written = (long long)Bb * KTOK * Dd + (long long)Bb * KTOK;
    for (long long i = written + blk * 192 + t; i < out_size;
         i += (long long)Bb * KTOK * 192)
        out[i] = 0.f;
}

// ---------------------------------------------------------------------------
extern "C" void kernel_launch(void* const* d_in, const int* in_sizes, int n_in,
                              void* d_out, int out_size) {
    const float* features = (const float*)d_in[0];
    const float* W1       = (const float*)d_in[1];
    const float* b1       = (const float*)d_in[2];
    const float* ln_gamma = (const float*)d_in[3];
    const float* ln_beta  = (const float*)d_in[4];
    const float* W2       = (const float*)d_in[5];
    const float* b2       = (const float*)d_in[6];
    float* out = (float*)d_out;

    cudaFuncSetAttribute(gemmscore_kernel,
                         cudaFuncAttributeMaxDynamicSharedMemorySize, SMEM_FUSED);

    convw_kernel<<<(Dd * Hh + 255) / 256, 256>>>(W1);                  // 1
    gemmscore_kernel<<<Mtot / GBM, 256, SMEM_FUSED>>>(                 // 2
        features, b1, ln_gamma, ln_beta, W2, b2);
    topk_kernel<<<Bb, 256>>>();                                        // 3
    rescore_gemm_kernel<<<512, 384>>>(features, b1);                   // 4 (ncu)
    lnselect_kernel<<<Bb, 384>>>(ln_gamma, ln_beta, W2, b2);           // 5
    gather_kernel<<<Bb * KTOK, 192>>>(features, out, (long long)out_size); // 6
}

// round 17
// speedup vs baseline: 1.1445x; 1.1445x over previous
#include <cuda_runtime.h>
#include <cuda_bf16.h>
#include <math.h>
#include <stdint.h>

// Problem shape (fixed)
#define Bb   16
#define Ss   4096
#define Dd   768
#define Hh   384
#define KTOK 40
#define KSEL 48
#define Mtot (Bb * Ss)   // 65536

// ---------------------------------------------------------------------------
// Device scratch
// ---------------------------------------------------------------------------
__device__ __nv_bfloat16 g_Wt [(size_t)Hh * Dd];  // W1^T bf16 [n][k]
__device__ float         g_scores[Mtot];          // pre-sigmoid approx scores
__device__ float         g_hex[(size_t)Bb * KSEL * Hh];
__device__ int           g_cand[Bb * KSEL];
__device__ int           g_idx[Bb * KTOK];

// ---------------------------------------------------------------------------
// helpers
// ---------------------------------------------------------------------------
__device__ __forceinline__ uint32_t smem_u32(const void* p) {
    uint32_t a;
    asm("{ .reg .u64 t; cvta.to.shared.u64 t, %1; cvt.u32.u64 %0, t; }"
        : "=r"(a) : "l"(p));
    return a;
}
__device__ __forceinline__ void cp16(uint32_t saddr, const void* gptr) {
    asm volatile("cp.async.cg.shared.global [%0], [%1], 16;"
                 :: "r"(saddr), "l"(gptr));
}
__device__ __forceinline__ void mma_bf16(float* c, const uint32_t* a,
                                         uint32_t b0, uint32_t b1) {
    asm volatile(
        "mma.sync.aligned.m16n8k16.row.col.f32.bf16.bf16.f32 "
        "{%0,%1,%2,%3}, {%4,%5,%6,%7}, {%8,%9}, {%0,%1,%2,%3};"
        : "+f"(c[0]), "+f"(c[1]), "+f"(c[2]), "+f"(c[3])
        : "r"(a[0]), "r"(a[1]), "r"(a[2]), "r"(a[3]), "r"(b0), "r"(b1));
}
#define LDSM4(r, addr)                                                         \
    asm volatile("ldmatrix.sync.aligned.m8n8.x4.shared.b16 "                   \
                 "{%0,%1,%2,%3}, [%4];"                                        \
                 : "=r"((r)[0]), "=r"((r)[1]), "=r"((r)[2]), "=r"((r)[3])      \
                 : "r"(addr))
// pack two f32 -> bf16x2 (low = x, high = y)
__device__ __forceinline__ uint32_t cvtpack(float x, float y) {
    uint32_t r;
    asm("cvt.rn.bf16x2.f32 %0, %1, %2;" : "=r"(r) : "f"(y), "f"(x));
    return r;
}

// ---------------------------------------------------------------------------
// Kernel 0: convert + transpose W1 [768,384] f32 -> g_Wt (bf16)
// ---------------------------------------------------------------------------
__global__ void convw_kernel(const float* __restrict__ W1) {
    int i = blockIdx.x * blockDim.x + threadIdx.x;
    if (i >= Dd * Hh) return;
    int k = i / Hh, n = i % Hh;
    g_Wt[(size_t)n * Dd + k] = __float2bfloat16_rn(W1[i]);
}

// ---------------------------------------------------------------------------
// Fused GEMM + score kernel (proven best — DO NOT TOUCH).
// ---------------------------------------------------------------------------
#define GBM 64
#define GBK 32
#define NCH (Dd / GBK)          // 24
#define APITCH 176
#define ABPITCH 80
#define BPITCH 80
#define ABUF (GBM * APITCH)             // 11264
#define ABBUF (GBM * ABPITCH)           // 5120
#define BBUF (Hh * BPITCH)              // 30720
#define OFF_AB (2 * ABUF)               // 22528
#define OFF_B (OFF_AB + ABBUF)          // 27648
#define SMEM_FUSED (OFF_B + 2 * BBUF)   // 89088
#define EPITCH 388

__global__ void __launch_bounds__(256, 2)
gemmscore_kernel(const float* __restrict__ A,  const float* __restrict__ b1,
                 const float* __restrict__ gamma, const float* __restrict__ beta,
                 const float* __restrict__ W2, const float* __restrict__ b2) {
    extern __shared__ char smem[];
    const uint32_t sb = smem_u32(smem);
    const int tid  = threadIdx.x;
    const int lane = tid & 31, wid = tid >> 5;
    const int wm = wid >> 2, wn = wid & 3;
    const int m0 = blockIdx.x * GBM;
    const int qt = lane & 3, rt = lane >> 2;

    float acc[2][12][4];
    #pragma unroll
    for (int mi = 0; mi < 2; mi++)
        #pragma unroll
        for (int ni = 0; ni < 12; ni++)
            #pragma unroll
            for (int j = 0; j < 4; j++) acc[mi][ni][j] = 0.f;

    const int ar = tid >> 3, aj = tid & 7;
    const int ar2 = (tid + 256) >> 3, aj2 = (tid + 256) & 7;

    const int lmat = lane >> 3, lrin = lane & 7;
    const int a_row = (lmat & 1) * 8 + lrin;
    const int a_khi = (lmat >> 1) * 8;
    const int b_row = (lmat >> 1) * 8 + lrin;
    const int b_khi = (lmat & 1) * 8;

    const uint32_t a_addr0 = sb + OFF_AB + (wm * 32 + a_row) * ABPITCH + a_khi * 2;
    const uint32_t a_addr1 = a_addr0 + 16 * ABPITCH;
    const uint32_t b_base  = sb + OFF_B + (wn * 96 + b_row) * BPITCH + b_khi * 2;

    const int cvr = tid >> 2, cvs = tid & 3;

    cp16(sb + ar  * APITCH + aj  * 16, A + (size_t)(m0 + ar)  * Dd + aj  * 4);
    cp16(sb + ar2 * APITCH + aj2 * 16, A + (size_t)(m0 + ar2) * Dd + aj2 * 4);
    #pragma unroll
    for (int i = 0; i < 6; i++) {
        int f = tid + i * 256;
        int n = f >> 2, j = f & 3;
        cp16(sb + OFF_B + n * BPITCH + j * 16, g_Wt + (size_t)n * Dd + j * 8);
    }
    asm volatile("cp.async.commit_group;");

    for (int c = 0; c < NCH; c++) {
        const int s = c & 1;

        if (c + 1 < NCH) {
            const int s1 = (c + 1) & 1;
            const int ko = (c + 1) * GBK;
            cp16(sb + s1 * ABUF + ar  * APITCH + aj  * 16,
                 A + (size_t)(m0 + ar)  * Dd + ko + aj  * 4);
            cp16(sb + s1 * ABUF + ar2 * APITCH + aj2 * 16,
                 A + (size_t)(m0 + ar2) * Dd + ko + aj2 * 4);
            #pragma unroll
            for (int i = 0; i < 6; i++) {
                int f = tid + i * 256;
                int n = f >> 2, j = f & 3;
                cp16(sb + OFF_B + s1 * BBUF + n * BPITCH + j * 16,
                     g_Wt + (size_t)n * Dd + ko + j * 8);
            }
            asm volatile("cp.async.commit_group;");
            asm volatile("cp.async.wait_group 1;");
        } else {
            asm volatile("cp.async.wait_group 0;");
        }
        __syncthreads();

        {
            const char* src = smem + s * ABUF + cvr * APITCH + cvs * 32;
            float4 v0 = *(const float4*)(src);
            float4 v1 = *(const float4*)(src + 16);
            uint4 p;
            p.x = cvtpack(v0.x, v0.y);
            p.y = cvtpack(v0.z, v0.w);
            p.z = cvtpack(v1.x, v1.y);
            p.w = cvtpack(v1.z, v1.w);
            *(uint4*)(smem + OFF_AB + cvr * ABPITCH + cvs * 16) = p;
        }
        __syncthreads();

        const uint32_t bks = b_base + s * BBUF;

        #pragma unroll
        for (int ks = 0; ks < 2; ks++) {
            const int kb2 = ks * 32;
            uint32_t afr[2][4];
            LDSM4(afr[0], a_addr0 + kb2);
            LDSM4(afr[1], a_addr1 + kb2);
            uint32_t bfr[2][4];
            LDSM4(bfr[0], bks + kb2);
            #pragma unroll
            for (int np = 0; np < 6; np++) {
                if (np < 5)
                    LDSM4(bfr[(np + 1) & 1], bks + (np + 1) * (16 * BPITCH) + kb2);
                const uint32_t* bf = bfr[np & 1];
                mma_bf16(acc[0][2 * np],     afr[0], bf[0], bf[1]);
                mma_bf16(acc[0][2 * np + 1], afr[0], bf[2], bf[3]);
                mma_bf16(acc[1][2 * np],     afr[1], bf[0], bf[1]);
                mma_bf16(acc[1][2 * np + 1], afr[1], bf[2], bf[3]);
            }
        }
        __syncthreads();
    }

    float* eb = (float*)smem;
    float gm[12], bt[12], w2r[12], b1r[12];
    #pragma unroll
    for (int i = 0; i < 12; i++) {
        int j = lane + 32 * i;
        gm[i]  = gamma[j];
        bt[i]  = beta[j];
        w2r[i] = W2[j];
        b1r[i] = b1[j];
    }
    const float b2v = b2[0];

    #pragma unroll
    for (int p = 0; p < 2; p++) {
        if (wm == p) {
            #pragma unroll
            for (int mi = 0; mi < 2; mi++) {
                #pragma unroll
                for (int ni = 0; ni < 12; ni++) {
                    int rl  = mi * 16 + rt;
                    int col = wn * 96 + ni * 8 + 2 * qt;
                    *(float2*)&eb[rl * EPITCH + col] =
                        make_float2(acc[mi][ni][0], acc[mi][ni][1]);
                    *(float2*)&eb[(rl + 8) * EPITCH + col] =
                        make_float2(acc[mi][ni][2], acc[mi][ni][3]);
                }
            }
        }
        __syncthreads();
        #pragma unroll
        for (int rr = 0; rr < 4; rr++) {
            const int rowl = wid * 4 + rr;
            float x[12];
            float sum = 0.f;
            #pragma unroll
            for (int i = 0; i < 12; i++) {
                x[i] = eb[rowl * EPITCH + lane + 32 * i] + b1r[i];
                sum += x[i];
            }
            #pragma unroll
            for (int o = 16; o > 0; o >>= 1) sum += __shfl_xor_sync(0xffffffffu, sum, o);
            const float mu = sum * (1.0f / Hh);
            float sq = 0.f;
            #pragma unroll
            for (int i = 0; i < 12; i++) { float d = x[i] - mu; sq += d * d; }
            #pragma unroll
            for (int o = 16; o > 0; o >>= 1) sq += __shfl_xor_sync(0xffffffffu, sq, o);
            const float rstd = 1.0f / sqrtf(sq * (1.0f / Hh) + 1e-5f);
            float dot = 0.f;
            #pragma unroll
            for (int i = 0; i < 12; i++) {
                float xn = (x[i] - mu) * rstd * gm[i] + bt[i];
                float ge = 0.5f * xn * (1.0f + erff(xn * 0.70710678118654752f));
                dot += ge * w2r[i];
            }
            #pragma unroll
            for (int o = 16; o > 0; o >>= 1) dot += __shfl_xor_sync(0xffffffffu, dot, o);
            if (lane == 0)
                g_scores[m0 + p * 32 + rowl] = dot + b2v;
        }
        __syncthreads();
    }
}

// ---------------------------------------------------------------------------
// monotonic u64 key: (order-preserving f32) << 32 | (Ss-1-i)  (tie -> low i)
// ---------------------------------------------------------------------------
__device__ __forceinline__ unsigned long long score_key(float f, int i) {
    uint32_t b = __float_as_uint(f);
    uint32_t flip = (b & 0x80000000u) ? ~b : (b | 0x80000000u);
    return ((unsigned long long)flip << 32) | (uint32_t)(Ss - 1 - i);
}

// ---------------------------------------------------------------------------
// top-48 per batch with per-warp max caching (proven — DO NOT TOUCH).
// ---------------------------------------------------------------------------
__global__ void __launch_bounds__(256)
topk_kernel() {
    __shared__ float s[Ss];
    __shared__ unsigned long long wkey[8];
    __shared__ int sbw;
    const int b = blockIdx.x;
    const int t = threadIdx.x;
    const int lane = t & 31, wid = t >> 5;

    for (int i = t; i < Ss; i += 256) s[i] = g_scores[b * Ss + i];
    __syncthreads();

    {
        unsigned long long best = 0ull;
        #pragma unroll
        for (int u = 0; u < 16; u++) {
            int i = wid * 512 + u * 32 + lane;
            unsigned long long k = score_key(s[i], i);
            if (k > best) best = k;
        }
        #pragma unroll
        for (int o = 16; o > 0; o >>= 1) {
            unsigned long long ok = __shfl_xor_sync(0xffffffffu, best, o);
            if (ok > best) best = ok;
        }
        if (lane == 0) wkey[wid] = best;
    }
    __syncthreads();

    for (int sel = 0; sel < KSEL; sel++) {
        if (t < 8) {
            unsigned long long v = wkey[t];
            int w = t;
            #pragma unroll
            for (int o = 4; o > 0; o >>= 1) {
                unsigned long long ov = __shfl_xor_sync(0xffu, v, o, 8);
                int ow = __shfl_xor_sync(0xffu, w, o, 8);
                if (ov > v) { v = ov; w = ow; }
            }
            if (t == 0) {
                int idx = Ss - 1 - (int)(v & 0xFFFFFFFFu);
                g_cand[b * KSEL + sel] = idx;
                s[idx] = -3e38f;
                sbw = w;
            }
        }
        __syncthreads();
        const int wb = sbw;
        if (wid == wb) {
            unsigned long long best = 0ull;
            #pragma unroll
            for (int u = 0; u < 16; u++) {
                int i = wb * 512 + u * 32 + lane;
                unsigned long long k = score_key(s[i], i);
                if (k > best) best = k;
            }
            #pragma unroll
            for (int o = 16; o > 0; o >>= 1) {
                unsigned long long ok = __shfl_xor_sync(0xffffffffu, best, o);
                if (ok > best) best = ok;
            }
            if (lane == 0) wkey[wb] = best;
        }
        __syncthreads();
    }
}

// ---------------------------------------------------------------------------
// rescore GEMM v4: exact fp32 h, W read COALESCED from W1's native [k][n]
//   layout (adjacent lanes -> adjacent columns: 2 lines/warp-load vs 32).
//   256 blocks = (batch 16) x (token-group 4, 12 tokens) x (col-quarter 4).
//   384 threads = (k-eighth 8) x (col-pair 48).
// ---------------------------------------------------------------------------
__global__ void __launch_bounds__(384)
rescore_gemm_kernel(const float* __restrict__ features,
                    const float* __restrict__ W1,
                    const float* __restrict__ b1) {
    extern __shared__ char rsm[];
    float* feat = (float*)rsm;                 // 12 x 768
    float* part = feat + 12 * Dd;              // 8 x 12 x 96

    const int blk = blockIdx.x;
    const int b   = blk >> 4;
    const int grp = (blk >> 2) & 3;
    const int cq  = blk & 3;
    const int t = threadIdx.x;
    const int kq = t / 48;                     // 0..7
    const int cp = t % 48;                     // col pair 0..47
    const int c0l = cp * 2;
    const int col0 = cq * 96 + c0l;

    const int cbase = b * KSEL + grp * 12;
    for (int j = 0; j < 12; j++) {
        int tok = g_cand[cbase + j];
        const float* src = features + ((size_t)b * Ss + tok) * Dd;
        for (int k = t; k < Dd; k += 384) feat[j * Dd + k] = src[k];
    }
    __syncthreads();

    float acc[12][2];
    #pragma unroll
    for (int j = 0; j < 12; j++) { acc[j][0] = 0.f; acc[j][1] = 0.f; }

    const float* wbase = W1 + (size_t)(kq * 96) * Hh + col0;  // [k][n], coalesced
    const float* fbase = feat + kq * 96;
    #pragma unroll 4
    for (int k = 0; k < 96; k++) {
        float2 w = *(const float2*)(wbase + (size_t)k * Hh);
        #pragma unroll
        for (int j = 0; j < 12; j++) {
            float f = fbase[j * Dd + k];       // warp-broadcast LDS
            acc[j][0] = fmaf(f, w.x, acc[j][0]);
            acc[j][1] = fmaf(f, w.y, acc[j][1]);
        }
    }
    #pragma unroll
    for (int j = 0; j < 12; j++) {
        part[(kq * 12 + j) * 96 + c0l]     = acc[j][0];
        part[(kq * 12 + j) * 96 + c0l + 1] = acc[j][1];
    }
    __syncthreads();

    for (int idx = t; idx < 12 * 96; idx += 384) {
        int j = idx / 96, c = idx % 96;
        float h = b1[cq * 96 + c];
        #pragma unroll
        for (int q = 0; q < 8; q++) h += part[(q * 12 + j) * 96 + c];
        g_hex[(size_t)(cbase + j) * Hh + cq * 96 + c] = h;
    }
}
#define SMEM_RGEMM ((12 * Dd + 8 * 12 * 96) * 4)   // 73728 B

// ---------------------------------------------------------------------------
// merged rescore-LN + warp-parallel select: 16 blocks, 384 threads (proven).
// ---------------------------------------------------------------------------
__global__ void __launch_bounds__(384)
lnselect_kernel(const float* __restrict__ gamma, const float* __restrict__ beta,
                const float* __restrict__ W2, const float* __restrict__ b2) {
    __shared__ unsigned long long skey[KSEL];
    const int b    = blockIdx.x;
    const int lane = threadIdx.x & 31, wid = threadIdx.x >> 5;
    const float b2v = b2[0];

    for (int r = 0; r < 4; r++) {
        const int ci   = wid * 4 + r;          // 0..47
        const int cand = b * KSEL + ci;
        const float* row = g_hex + (size_t)cand * Hh;

        float x[12];
        float sum = 0.f;
        #pragma unroll
        for (int i = 0; i < 12; i++) { x[i] = row[lane + 32 * i]; sum += x[i]; }
        #pragma unroll
        for (int o = 16; o > 0; o >>= 1) sum += __shfl_xor_sync(0xffffffffu, sum, o);
        const float mu = sum * (1.0f / Hh);
        float sq = 0.f;
        #pragma unroll
        for (int i = 0; i < 12; i++) { float d = x[i] - mu; sq += d * d; }
        #pragma unroll
        for (int o = 16; o > 0; o >>= 1) sq += __shfl_xor_sync(0xffffffffu, sq, o);
        const float rstd = 1.0f / sqrtf(sq * (1.0f / Hh) + 1e-5f);
        float dot = 0.f;
        #pragma unroll
        for (int i = 0; i < 12; i++) {
            float xn = (x[i] - mu) * rstd * gamma[lane + 32 * i] + beta[lane + 32 * i];
            float ge = 0.5f * xn * (1.0f + erff(xn * 0.70710678118654752f));
            dot += ge * W2[lane + 32 * i];
        }
        #pragma unroll
        for (int o = 16; o > 0; o >>= 1) dot += __shfl_xor_sync(0xffffffffu, dot, o);
        if (lane == 0)
            skey[ci] = score_key(dot + b2v, g_cand[b * KSEL + ci]);
    }
    __syncthreads();

    if (wid == 0) {
        unsigned long long k0 = skey[lane];
        unsigned long long k1 = (lane < KSEL - 32) ? skey[lane + 32] : 0ull;
        for (int sel = 0; sel < KTOK; sel++) {
            unsigned long long m = (k0 > k1) ? k0 : k1;
            unsigned long long w = m;
            #pragma unroll
            for (int o = 16; o > 0; o >>= 1) {
                unsigned long long ow = __shfl_xor_sync(0xffffffffu, w, o);
                if (ow > w) w = ow;
            }
            if (lane == 0)
                g_idx[b * KTOK + sel] = Ss - 1 - (int)(w & 0xFFFFFFFFu);
            if (k0 == w) k0 = 0ull;
            if (k1 == w) k1 = 0ull;
        }
    }
}

// ---------------------------------------------------------------------------
// gather tokens + indices into d_out; each block also zeroes a tail slice
// ---------------------------------------------------------------------------
__global__ void __launch_bounds__(192)
gather_kernel(const float* __restrict__ features, float* __restrict__ out,
              long long out_size) {
    const int blk = blockIdx.x;
    const int b   = blk / KTOK;
    const int tok = g_idx[blk];
    const int t   = threadIdx.x;
    long long base = (long long)blk * Dd;
    if (base + (t + 1) * 4 <= out_size) {
        const float4* src = (const float4*)(features + ((size_t)b * Ss + tok) * Dd);
        ((float4*)(out + base))[t] = src[t];
    }
    if (t == 0) {
        long long pos = (long long)Bb * KTOK * Dd + blk;
        if (pos < out_size) out[pos] = (float)tok;
    }
    const long long written = (long long)Bb * KTOK * Dd + (long long)Bb * KTOK;
    for (long long i = written + blk * 192 + t; i < out_size;
         i += (long long)Bb * KTOK * 192)
        out[i] = 0.f;
}

// ---------------------------------------------------------------------------
extern "C" void kernel_launch(void* const* d_in, const int* in_sizes, int n_in,
                              void* d_out, int out_size) {
    const float* features = (const float*)d_in[0];
    const float* W1       = (const float*)d_in[1];
    const float* b1       = (const float*)d_in[2];
    const float* ln_gamma = (const float*)d_in[3];
    const float* ln_beta  = (const float*)d_in[4];
    const float* W2       = (const float*)d_in[5];
    const float* b2       = (const float*)d_in[6];
    float* out = (float*)d_out;

    cudaFuncSetAttribute(gemmscore_kernel,
                         cudaFuncAttributeMaxDynamicSharedMemorySize, SMEM_FUSED);
    cudaFuncSetAttribute(rescore_gemm_kernel,
                         cudaFuncAttributeMaxDynamicSharedMemorySize, SMEM_RGEMM);

    convw_kernel<<<(Dd * Hh + 255) / 256, 256>>>(W1);                  // 1
    gemmscore_kernel<<<Mtot / GBM, 256, SMEM_FUSED>>>(                 // 2
        features, b1, ln_gamma, ln_beta, W2, b2);
    topk_kernel<<<Bb, 256>>>();                                        // 3
    rescore_gemm_kernel<<<256, 384, SMEM_RGEMM>>>(features, W1, b1);   // 4 (ncu)
    lnselect_kernel<<<Bb, 384>>>(ln_gamma, ln_beta, W2, b2);           // 5
    gather_kernel<<<Bb * KTOK, 192>>>(features, out, (long long)out_size); // 6
}